// round 1
// baseline (speedup 1.0000x reference)
#include <cuda_runtime.h>
#include <cstdint>

#define HH 50
#define DD 64
#define NTHREADS 128

__global__ void zero_tail_kernel(float* __restrict__ out, int off) {
    if (threadIdx.x == 0) { out[off] = 0.f; out[off + 1] = 0.f; }
}

__global__ void __launch_bounds__(NTHREADS) fused_kernel(
    const int* __restrict__ user1, const int* __restrict__ item1,
    const int* __restrict__ user2, const int* __restrict__ item2,
    const int* __restrict__ u_his, const int* __restrict__ u_pos, const int* __restrict__ u_mask,
    const int* __restrict__ i_his, const int* __restrict__ i_pos, const int* __restrict__ i_mask,
    const float* __restrict__ user1_emb, const float* __restrict__ item1_emb,
    const float* __restrict__ user1_bias, const float* __restrict__ item1_bias,
    const float* __restrict__ u_pos_emb,
    const float* __restrict__ user2_emb, const float* __restrict__ item2_emb,
    const float* __restrict__ user2_bias, const float* __restrict__ item2_bias,
    const float* __restrict__ i_pos_emb,
    const float* __restrict__ attn_u_W, const float* __restrict__ attn_u_b,
    const float* __restrict__ attn_i_W, const float* __restrict__ attn_i_b,
    float* __restrict__ out, int B)
{
    __shared__ float Ku[HH * DD];          // u-branch attention keys (shared by 2 queries)
    __shared__ float Ki[HH * DD];          // i-branch attention keys
    __shared__ float kdU[HH], kdI[HH];     // key-side score dot: K[h] . Wk
    __shared__ float swu[2 * DD], swi[2 * DD];
    __shared__ int   sih_u[HH], sip_u[HH], sih_i[HH], sip_i[HH];
    __shared__ float sm_u[HH], sm_i[HH];
    __shared__ float sred1[4], sred2[4];

    const int tid = threadIdx.x;
    const int b   = blockIdx.x;

    if (tid < 2 * DD) { swu[tid] = attn_u_W[tid]; swi[tid] = attn_i_W[tid]; }
    if (tid < HH) {
        sih_u[tid] = u_his[b * HH + tid];
        sip_u[tid] = u_pos[b * HH + tid];
        sm_u[tid]  = (u_mask[b * HH + tid] != 0) ? 1.f : 0.f;
        sih_i[tid] = i_his[b * HH + tid];
        sip_i[tid] = i_pos[b * HH + tid];
        sm_i[tid]  = (i_mask[b * HH + tid] != 0) ? 1.f : 0.f;
    }
    __syncthreads();

    float reg1 = 0.f, reg2 = 0.f;
    const int g   = tid >> 4;   // 8 groups, one key-row each per pass
    const int l16 = tid & 15;   // 16 float4 lanes per row

    // ---- gather Ku = (item1_emb[u_his] + u_pos_emb[u_pos]) * mu ; fused kdot + reg1 ----
    {
        const float4 wk = ((const float4*)(swu + DD))[l16];
        #pragma unroll
        for (int pass = 0; pass < 7; ++pass) {
            int h = pass * 8 + g;
            bool v = h < HH;
            int ih = v ? sih_u[h] : 0;
            int ip = v ? sip_u[h] : 0;
            float m = v ? sm_u[h] : 0.f;
            float4 e = ((const float4*)item1_emb)[(size_t)ih * 16 + l16];
            float4 p = ((const float4*)u_pos_emb)[ip * 16 + l16];
            reg1 += m * (e.x * e.x + e.y * e.y + e.z * e.z + e.w * e.w);
            float4 k;
            k.x = (e.x + p.x) * m; k.y = (e.y + p.y) * m;
            k.z = (e.z + p.z) * m; k.w = (e.w + p.w) * m;
            if (v) ((float4*)(Ku + h * DD))[l16] = k;
            float part = k.x * wk.x + k.y * wk.y + k.z * wk.z + k.w * wk.w;
            #pragma unroll
            for (int o = 8; o; o >>= 1) part += __shfl_down_sync(0xffffffffu, part, o, 16);
            if (v && l16 == 0) kdU[h] = part;
        }
    }
    // ---- gather Ki = (user2_emb[i_his] + i_pos_emb[i_pos]) * mi ; fused kdot + reg2 ----
    {
        const float4 wk = ((const float4*)(swi + DD))[l16];
        #pragma unroll
        for (int pass = 0; pass < 7; ++pass) {
            int h = pass * 8 + g;
            bool v = h < HH;
            int ih = v ? sih_i[h] : 0;
            int ip = v ? sip_i[h] : 0;
            float m = v ? sm_i[h] : 0.f;
            float4 e = ((const float4*)user2_emb)[(size_t)ih * 16 + l16];
            float4 p = ((const float4*)i_pos_emb)[ip * 16 + l16];
            reg2 += m * (e.x * e.x + e.y * e.y + e.z * e.z + e.w * e.w);
            float4 k;
            k.x = (e.x + p.x) * m; k.y = (e.y + p.y) * m;
            k.z = (e.z + p.z) * m; k.w = (e.w + p.w) * m;
            if (v) ((float4*)(Ki + h * DD))[l16] = k;
            float part = k.x * wk.x + k.y * wk.y + k.z * wk.z + k.w * wk.w;
            #pragma unroll
            for (int o = 8; o; o >>= 1) part += __shfl_down_sync(0xffffffffu, part, o, 16);
            if (v && l16 == 0) kdI[h] = part;
        }
    }
    __syncthreads();

    // ---- 4 attention tasks, one warp each ----
    const int warp = tid >> 5, lane = tid & 31;
    const int i1 = item1[b], u1 = user1[b], i2 = item2[b], u2 = user2[b];

    const float *Kt, *kd, *wv, *Q, *Av, *Bv;
    float batt, bsum;
    int ooff;
    if (warp == 0) {            // u_ds: query i1s -> logits_us
        Kt = Ku; kd = kdU; wv = swu; batt = attn_u_b[0];
        Q  = item1_emb + (size_t)i1 * DD;
        Av = Q;                                   // + i1s
        Bv = user1_emb + (size_t)u1 * DD;         // . u1s
        bsum = user1_bias[u1] + item1_bias[i1];
        ooff = b;                                 // logits_us
    } else if (warp == 1) {     // u_dr: query i1r -> logits_ur
        Kt = Ku; kd = kdU; wv = swu; batt = attn_u_b[0];
        Q  = item2_emb + (size_t)i1 * DD;
        Av = item1_emb + (size_t)i2 * DD;         // + i2r
        Bv = user1_emb + (size_t)u2 * DD;         // . u2r
        bsum = user1_bias[u2] + item1_bias[i2];
        ooff = 2 * B + b;                         // logits_ur
    } else if (warp == 2) {     // i_dr: query u1r -> logits_ir
        Kt = Ki; kd = kdI; wv = swi; batt = attn_i_b[0];
        Q  = user2_emb + (size_t)u1 * DD;
        Av = item2_emb + (size_t)i1 * DD;         // + i1r
        Bv = Q;                                   // . u1r
        bsum = user2_bias[u1] + item2_bias[i1];
        ooff = B + b;                             // logits_ir
    } else {                    // i_ds: query u1s -> logits_is
        Kt = Ki; kd = kdI; wv = swi; batt = attn_i_b[0];
        Q  = user1_emb + (size_t)u1 * DD;
        Av = item2_emb + (size_t)i2 * DD;         // + i2s
        Bv = user2_emb + (size_t)u2 * DD;         // . u2s
        bsum = user2_bias[u2] + item2_bias[i2];
        ooff = 3 * B + b;                         // logits_is
    }

    float q0 = Q[lane], q1 = Q[lane + 32];
    float cq = q0 * wv[lane] + q1 * wv[lane + 32];
    #pragma unroll
    for (int o = 16; o; o >>= 1) cq += __shfl_xor_sync(0xffffffffu, cq, o);
    cq += batt;

    float s0 = (lane < HH)      ? tanhf(cq + kd[lane])      : -1e30f;
    float s1 = (lane + 32 < HH) ? tanhf(cq + kd[lane + 32]) : -1e30f;
    float mx = fmaxf(s0, s1);
    #pragma unroll
    for (int o = 16; o; o >>= 1) mx = fmaxf(mx, __shfl_xor_sync(0xffffffffu, mx, o));
    float e0 = (lane < HH)      ? __expf(s0 - mx) : 0.f;
    float e1 = (lane + 32 < HH) ? __expf(s1 - mx) : 0.f;
    float se = e0 + e1;
    #pragma unroll
    for (int o = 16; o; o >>= 1) se += __shfl_xor_sync(0xffffffffu, se, o);
    float inv = 1.f / se;
    float w0 = e0 * inv, w1 = e1 * inv;

    float acc0 = 0.f, acc1 = 0.f;
    #pragma unroll
    for (int h = 0; h < 32; ++h) {
        float wh = __shfl_sync(0xffffffffu, w0, h);
        acc0 += wh * Kt[h * DD + lane];
        acc1 += wh * Kt[h * DD + lane + 32];
    }
    #pragma unroll
    for (int h = 32; h < HH; ++h) {
        float wh = __shfl_sync(0xffffffffu, w1, h - 32);
        acc0 += wh * Kt[h * DD + lane];
        acc1 += wh * Kt[h * DD + lane + 32];
    }

    float a0 = Av[lane], a1 = Av[lane + 32];
    float b0 = Bv[lane], b1 = Bv[lane + 32];
    float lg = (acc0 + a0) * b0 + (acc1 + a1) * b1;
    #pragma unroll
    for (int o = 16; o; o >>= 1) lg += __shfl_xor_sync(0xffffffffu, lg, o);
    if (lane == 0) out[ooff] = lg + bsum;

    // reg-loss vector parts: reg1 += ||u1s||^2+||i1s||^2 ; reg2 += ||u2s||^2+||i2s||^2
    if (warp == 0) reg1 += q0 * q0 + q1 * q1 + b0 * b0 + b1 * b1;   // i1s, u1s
    if (warp == 3) reg2 += a0 * a0 + a1 * a1 + b0 * b0 + b1 * b1;   // i2s, u2s

    #pragma unroll
    for (int o = 16; o; o >>= 1) {
        reg1 += __shfl_xor_sync(0xffffffffu, reg1, o);
        reg2 += __shfl_xor_sync(0xffffffffu, reg2, o);
    }
    if (lane == 0) { sred1[warp] = reg1; sred2[warp] = reg2; }
    __syncthreads();
    if (tid == 0) {
        atomicAdd(out + 4 * B,     sred1[0] + sred1[1] + sred1[2] + sred1[3]);
        atomicAdd(out + 4 * B + 1, sred2[0] + sred2[1] + sred2[2] + sred2[3]);
    }
}

extern "C" void kernel_launch(void* const* d_in, const int* in_sizes, int n_in,
                              void* d_out, int out_size) {
    const int B = in_sizes[0];
    float* out = (float*)d_out;

    zero_tail_kernel<<<1, 32>>>(out, 4 * B);
    fused_kernel<<<B, NTHREADS>>>(
        (const int*)d_in[0], (const int*)d_in[1], (const int*)d_in[2], (const int*)d_in[3],
        (const int*)d_in[4], (const int*)d_in[5], (const int*)d_in[6],
        (const int*)d_in[7], (const int*)d_in[8], (const int*)d_in[9],
        (const float*)d_in[10], (const float*)d_in[11],
        (const float*)d_in[12], (const float*)d_in[13],
        (const float*)d_in[14],
        (const float*)d_in[15], (const float*)d_in[16],
        (const float*)d_in[17], (const float*)d_in[18],
        (const float*)d_in[19],
        (const float*)d_in[20], (const float*)d_in[21],
        (const float*)d_in[22], (const float*)d_in[23],
        out, B);
}

// round 6
// speedup vs baseline: 1.0811x; 1.0811x over previous
#include <cuda_runtime.h>
#include <cstdint>

#define HH 50
#define DD 64
#define NT 128

__global__ void zero_tail_kernel(float* __restrict__ out, int off) {
    if (threadIdx.x == 0) { out[off] = 0.f; out[off + 1] = 0.f; }
}

__global__ void __launch_bounds__(NT) fused_kernel(
    const int* __restrict__ user1, const int* __restrict__ item1,
    const int* __restrict__ user2, const int* __restrict__ item2,
    const int* __restrict__ u_his, const int* __restrict__ u_pos, const int* __restrict__ u_mask,
    const int* __restrict__ i_his, const int* __restrict__ i_pos, const int* __restrict__ i_mask,
    const float* __restrict__ user1_emb, const float* __restrict__ item1_emb,
    const float* __restrict__ user1_bias, const float* __restrict__ item1_bias,
    const float* __restrict__ u_pos_emb,
    const float* __restrict__ user2_emb, const float* __restrict__ item2_emb,
    const float* __restrict__ user2_bias, const float* __restrict__ item2_bias,
    const float* __restrict__ i_pos_emb,
    const float* __restrict__ attn_u_W, const float* __restrict__ attn_u_b,
    const float* __restrict__ attn_i_W, const float* __restrict__ attn_i_b,
    float* __restrict__ out, int B)
{
    __shared__ __align__(16) float K[HH * DD];
    __shared__ __align__(16) float sw[2 * DD];
    __shared__ float kd[HH];
    __shared__ float swgt[2][HH];
    __shared__ int   sih[HH], sip[HH];
    __shared__ float sm[HH];
    __shared__ float dpart[4][2][DD];
    __shared__ float sred[4];

    const int tid   = threadIdx.x;
    const int b     = blockIdx.x;
    const int phase = blockIdx.y;           // 0 = u-branch keys, 1 = i-branch keys
    const int warp  = tid >> 5, lane = tid & 31;
    const int g     = tid >> 4, l16  = tid & 15;

    const int u1 = user1[b], i1 = item1[b], u2 = user2[b], i2 = item2[b];

    const int*   his  = phase ? i_his  : u_his;
    const int*   pos  = phase ? i_pos  : u_pos;
    const int*   msk  = phase ? i_mask : u_mask;
    const float* emb  = phase ? user2_emb : item1_emb;
    const float* pemb = phase ? i_pos_emb : u_pos_emb;
    const float* W    = phase ? attn_i_W  : attn_u_W;
    const float  batt = phase ? attn_i_b[0] : attn_u_b[0];

    if (tid < HH) {
        sih[tid] = his[b * HH + tid];
        sip[tid] = pos[b * HH + tid];
        sm[tid]  = (msk[b * HH + tid] != 0) ? 1.f : 0.f;
    }
    sw[tid] = W[tid];
    __syncthreads();

    // ---- gather K = (emb[his] + pemb[pos]) * m ; fused key-dot + masked reg-norm ----
    float regacc = 0.f;
    {
        const float4 wk = ((const float4*)(sw + DD))[l16];
        #pragma unroll
        for (int pass = 0; pass < 7; ++pass) {
            int h = pass * 8 + g;
            bool v = h < HH;
            int ih = v ? sih[h] : 0;
            int ip = v ? sip[h] : 0;
            float m = v ? sm[h] : 0.f;
            float4 e = ((const float4*)emb)[(size_t)ih * 16 + l16];
            float4 p = ((const float4*)pemb)[ip * 16 + l16];
            regacc += m * (e.x * e.x + e.y * e.y + e.z * e.z + e.w * e.w);
            float4 k;
            k.x = (e.x + p.x) * m; k.y = (e.y + p.y) * m;
            k.z = (e.z + p.z) * m; k.w = (e.w + p.w) * m;
            if (v) ((float4*)(K + h * DD))[l16] = k;
            float part = k.x * wk.x + k.y * wk.y + k.z * wk.z + k.w * wk.w;
            #pragma unroll
            for (int o = 8; o; o >>= 1) part += __shfl_down_sync(0xffffffffu, part, o, 16);
            if (v && l16 == 0) kd[h] = part;
        }
    }
    __syncthreads();

    // ---- softmax weights for the 2 queries (warps 0,1) ----
    if (warp < 2) {
        const float* Q = phase
            ? (warp ? user1_emb + (size_t)u1 * DD : user2_emb + (size_t)u1 * DD)
            : (warp ? item2_emb + (size_t)i1 * DD : item1_emb + (size_t)i1 * DD);
        float q0 = Q[lane], q1 = Q[lane + 32];
        float cq = q0 * sw[lane] + q1 * sw[lane + 32];
        #pragma unroll
        for (int o = 16; o; o >>= 1) cq += __shfl_xor_sync(0xffffffffu, cq, o);
        cq += batt;

        float s0 = tanhf(cq + kd[lane]);
        float s1 = (lane + 32 < HH) ? tanhf(cq + kd[lane + 32]) : -1e30f;
        float mx = fmaxf(s0, s1);
        #pragma unroll
        for (int o = 16; o; o >>= 1) mx = fmaxf(mx, __shfl_xor_sync(0xffffffffu, mx, o));
        float e0 = __expf(s0 - mx);
        float e1 = (lane + 32 < HH) ? __expf(s1 - mx) : 0.f;
        float se = e0 + e1;
        #pragma unroll
        for (int o = 16; o; o >>= 1) se += __shfl_xor_sync(0xffffffffu, se, o);
        float inv = 1.f / se;
        swgt[warp][lane] = e0 * inv;
        if (lane + 32 < HH) swgt[warp][lane + 32] = e1 * inv;
    }
    __syncthreads();

    // ---- weighted sum: 4 warps split h, K read once, both queries per pass ----
    {
        int h0 = warp * 13;
        int h1 = (h0 + 13 < HH) ? h0 + 13 : HH;
        float a0 = 0.f, a1 = 0.f, c0 = 0.f, c1 = 0.f;
        for (int h = h0; h < h1; ++h) {
            float wA = swgt[0][h], wB = swgt[1][h];
            float k0 = K[h * DD + lane], k1 = K[h * DD + lane + 32];
            a0 += wA * k0; a1 += wA * k1;
            c0 += wB * k0; c1 += wB * k1;
        }
        dpart[warp][0][lane] = a0; dpart[warp][0][lane + 32] = a1;
        dpart[warp][1][lane] = c0; dpart[warp][1][lane + 32] = c1;
    }
    __syncthreads();

    // ---- final logits (warps 0,1) + reg-loss vector norms ----
    if (warp < 2) {
        float d0 = dpart[0][warp][lane] + dpart[1][warp][lane]
                 + dpart[2][warp][lane] + dpart[3][warp][lane];
        float d1 = dpart[0][warp][lane + 32] + dpart[1][warp][lane + 32]
                 + dpart[2][warp][lane + 32] + dpart[3][warp][lane + 32];

        const float *Av, *Bv; float bias; int ooff;
        if (phase == 0) {
            if (warp == 0) {   // logits_us
                Av = item1_emb + (size_t)i1 * DD; Bv = user1_emb + (size_t)u1 * DD;
                bias = user1_bias[u1] + item1_bias[i1]; ooff = b;
            } else {           // logits_ur
                Av = item1_emb + (size_t)i2 * DD; Bv = user1_emb + (size_t)u2 * DD;
                bias = user1_bias[u2] + item1_bias[i2]; ooff = 2 * B + b;
            }
        } else {
            if (warp == 0) {   // logits_ir
                Av = item2_emb + (size_t)i1 * DD; Bv = user2_emb + (size_t)u1 * DD;
                bias = user2_bias[u1] + item2_bias[i1]; ooff = B + b;
            } else {           // logits_is
                Av = item2_emb + (size_t)i2 * DD; Bv = user2_emb + (size_t)u2 * DD;
                bias = user2_bias[u2] + item2_bias[i2]; ooff = 3 * B + b;
            }
        }
        float av0 = Av[lane], av1 = Av[lane + 32];
        float bv0 = Bv[lane], bv1 = Bv[lane + 32];
        float lg = (d0 + av0) * bv0 + (d1 + av1) * bv1;
        #pragma unroll
        for (int o = 16; o; o >>= 1) lg += __shfl_xor_sync(0xffffffffu, lg, o);
        if (lane == 0) out[ooff] = lg + bias;

        // reg1 += ||u1s||^2+||i1s||^2 (phase0/warp0) ; reg2 += ||u2s||^2+||i2s||^2 (phase1/warp1)
        if ((phase == 0 && warp == 0) || (phase == 1 && warp == 1))
            regacc += av0 * av0 + av1 * av1 + bv0 * bv0 + bv1 * bv1;
    }

    // ---- block reduce reg loss, one atomic per block into out[4B + phase] ----
    #pragma unroll
    for (int o = 16; o; o >>= 1) regacc += __shfl_xor_sync(0xffffffffu, regacc, o);
    if (lane == 0) sred[warp] = regacc;
    __syncthreads();
    if (tid == 0)
        atomicAdd(out + 4 * B + phase, sred[0] + sred[1] + sred[2] + sred[3]);
}

extern "C" void kernel_launch(void* const* d_in, const int* in_sizes, int n_in,
                              void* d_out, int out_size) {
    const int B = in_sizes[0];
    float* out = (float*)d_out;

    zero_tail_kernel<<<1, 32>>>(out, 4 * B);
    fused_kernel<<<dim3(B, 2), NT>>>(
        (const int*)d_in[0], (const int*)d_in[1], (const int*)d_in[2], (const int*)d_in[3],
        (const int*)d_in[4], (const int*)d_in[5], (const int*)d_in[6],
        (const int*)d_in[7], (const int*)d_in[8], (const int*)d_in[9],
        (const float*)d_in[10], (const float*)d_in[11],
        (const float*)d_in[12], (const float*)d_in[13],
        (const float*)d_in[14],
        (const float*)d_in[15], (const float*)d_in[16],
        (const float*)d_in[17], (const float*)d_in[18],
        (const float*)d_in[19],
        (const float*)d_in[20], (const float*)d_in[21],
        (const float*)d_in[22], (const float*)d_in[23],
        out, B);
}

// round 7
// speedup vs baseline: 1.2388x; 1.1458x over previous
#include <cuda_runtime.h>
#include <cstdint>

#define HH 50
#define DD 64
#define NT 128

__global__ void zero_tail_kernel(float* __restrict__ out, int off) {
    if (threadIdx.x == 0) { out[off] = 0.f; out[off + 1] = 0.f; }
}

__global__ void __launch_bounds__(NT) fused_kernel(
    const int* __restrict__ user1, const int* __restrict__ item1,
    const int* __restrict__ user2, const int* __restrict__ item2,
    const int* __restrict__ u_his, const int* __restrict__ u_pos, const int* __restrict__ u_mask,
    const int* __restrict__ i_his, const int* __restrict__ i_pos, const int* __restrict__ i_mask,
    const float* __restrict__ user1_emb, const float* __restrict__ item1_emb,
    const float* __restrict__ user1_bias, const float* __restrict__ item1_bias,
    const float* __restrict__ u_pos_emb,
    const float* __restrict__ user2_emb, const float* __restrict__ item2_emb,
    const float* __restrict__ user2_bias, const float* __restrict__ item2_bias,
    const float* __restrict__ i_pos_emb,
    const float* __restrict__ attn_u_W, const float* __restrict__ attn_u_b,
    const float* __restrict__ attn_i_W, const float* __restrict__ attn_i_b,
    float* __restrict__ out, int B)
{
    __shared__ float kd[HH];
    __shared__ float swgt[2][HH];
    __shared__ __align__(16) float part[4][2][DD];   // per-warp partial d for 2 queries
    __shared__ float sred[4];

    const int tid   = threadIdx.x;
    const int b     = blockIdx.x;
    const int phase = blockIdx.y;            // 0 = u-branch keys, 1 = i-branch keys
    const int warp  = tid >> 5, lane = tid & 31;
    const int g     = tid >> 4, l16  = tid & 15;

    const int u1 = user1[b], i1 = item1[b], u2 = user2[b], i2 = item2[b];

    const int*   his  = phase ? i_his  : u_his;
    const int*   pos  = phase ? i_pos  : u_pos;
    const int*   msk  = phase ? i_mask : u_mask;
    const float* emb  = phase ? user2_emb : item1_emb;
    const float* pemb = phase ? i_pos_emb : u_pos_emb;
    const float* W    = phase ? attn_i_W  : attn_u_W;
    const float  batt = phase ? attn_i_b[0] : attn_u_b[0];

    // ---- gather: K stays in registers (7 float4/thread); fused key-dot + reg-norm ----
    float4 k4[7];
    float  regacc = 0.f;
    {
        const float4 wk = __ldg((const float4*)(W + DD) + l16);
        #pragma unroll
        for (int p = 0; p < 7; ++p) {
            const int h = p * 8 + g;
            if (h < HH) {
                int   ih = __ldg(his + b * HH + h);
                int   ip = __ldg(pos + b * HH + h);
                float m  = (__ldg(msk + b * HH + h) != 0) ? 1.f : 0.f;
                float4 e  = __ldg((const float4*)emb  + (size_t)ih * 16 + l16);
                float4 pp = __ldg((const float4*)pemb + (size_t)ip * 16 + l16);
                regacc += m * (e.x * e.x + e.y * e.y + e.z * e.z + e.w * e.w);
                k4[p].x = (e.x + pp.x) * m; k4[p].y = (e.y + pp.y) * m;
                k4[p].z = (e.z + pp.z) * m; k4[p].w = (e.w + pp.w) * m;
                float prt = k4[p].x * wk.x + k4[p].y * wk.y
                          + k4[p].z * wk.z + k4[p].w * wk.w;
                #pragma unroll
                for (int o = 8; o; o >>= 1) prt += __shfl_down_sync(0xffffffffu, prt, o, 16);
                if (l16 == 0) kd[h] = prt;
            } else {
                k4[p] = make_float4(0.f, 0.f, 0.f, 0.f);
            }
        }
    }
    __syncthreads();

    // ---- softmax weights for the 2 queries (warps 0,1) ----
    if (warp < 2) {
        const float* Q = phase
            ? (warp ? user1_emb + (size_t)u1 * DD : user2_emb + (size_t)u1 * DD)
            : (warp ? item2_emb + (size_t)i1 * DD : item1_emb + (size_t)i1 * DD);
        float q0 = __ldg(Q + lane), q1 = __ldg(Q + lane + 32);
        float cq = q0 * __ldg(W + lane) + q1 * __ldg(W + lane + 32);
        #pragma unroll
        for (int o = 16; o; o >>= 1) cq += __shfl_xor_sync(0xffffffffu, cq, o);
        cq += batt;

        float s0 = tanhf(cq + kd[lane]);
        float s1 = (lane + 32 < HH) ? tanhf(cq + kd[lane + 32]) : -1e30f;
        float mx = fmaxf(s0, s1);
        #pragma unroll
        for (int o = 16; o; o >>= 1) mx = fmaxf(mx, __shfl_xor_sync(0xffffffffu, mx, o));
        float e0 = __expf(s0 - mx);
        float e1 = (lane + 32 < HH) ? __expf(s1 - mx) : 0.f;
        float se = e0 + e1;
        #pragma unroll
        for (int o = 16; o; o >>= 1) se += __shfl_xor_sync(0xffffffffu, se, o);
        float inv = 1.f / se;
        swgt[warp][lane] = e0 * inv;
        if (lane + 32 < HH) swgt[warp][lane + 32] = e1 * inv;
    }
    __syncthreads();

    // ---- weighted sum fully in registers; cheap cross-group reduce ----
    {
        float4 aA = make_float4(0.f, 0.f, 0.f, 0.f);
        float4 aB = make_float4(0.f, 0.f, 0.f, 0.f);
        #pragma unroll
        for (int p = 0; p < 7; ++p) {
            const int h = p * 8 + g;
            if (h < HH) {
                float wA = swgt[0][h], wB = swgt[1][h];
                aA.x += wA * k4[p].x; aA.y += wA * k4[p].y;
                aA.z += wA * k4[p].z; aA.w += wA * k4[p].w;
                aB.x += wB * k4[p].x; aB.y += wB * k4[p].y;
                aB.z += wB * k4[p].z; aB.w += wB * k4[p].w;
            }
        }
        // combine lanes l and l+16 (groups 2w and 2w+1 within each warp)
        aA.x += __shfl_down_sync(0xffffffffu, aA.x, 16);
        aA.y += __shfl_down_sync(0xffffffffu, aA.y, 16);
        aA.z += __shfl_down_sync(0xffffffffu, aA.z, 16);
        aA.w += __shfl_down_sync(0xffffffffu, aA.w, 16);
        aB.x += __shfl_down_sync(0xffffffffu, aB.x, 16);
        aB.y += __shfl_down_sync(0xffffffffu, aB.y, 16);
        aB.z += __shfl_down_sync(0xffffffffu, aB.z, 16);
        aB.w += __shfl_down_sync(0xffffffffu, aB.w, 16);
        if (lane < 16) {
            ((float4*)part[warp][0])[l16] = aA;
            ((float4*)part[warp][1])[l16] = aB;
        }
    }
    __syncthreads();

    // ---- fold 4 warp-partials, final logits (warps 0,1) + reg-loss vector norms ----
    if (warp < 2) {
        const int q = warp;
        float d0 = 0.f, d1 = 0.f;
        #pragma unroll
        for (int w = 0; w < 4; ++w) {
            float2 t = *(const float2*)&part[w][q][2 * lane];
            d0 += t.x; d1 += t.y;
        }

        const float *Av, *Bv; float bias; int ooff;
        if (phase == 0) {
            if (q == 0) {      // logits_us
                Av = item1_emb + (size_t)i1 * DD; Bv = user1_emb + (size_t)u1 * DD;
                bias = user1_bias[u1] + item1_bias[i1]; ooff = b;
            } else {           // logits_ur
                Av = item1_emb + (size_t)i2 * DD; Bv = user1_emb + (size_t)u2 * DD;
                bias = user1_bias[u2] + item1_bias[i2]; ooff = 2 * B + b;
            }
        } else {
            if (q == 0) {      // logits_ir
                Av = item2_emb + (size_t)i1 * DD; Bv = user2_emb + (size_t)u1 * DD;
                bias = user2_bias[u1] + item2_bias[i1]; ooff = B + b;
            } else {           // logits_is
                Av = item2_emb + (size_t)i2 * DD; Bv = user2_emb + (size_t)u2 * DD;
                bias = user2_bias[u2] + item2_bias[i2]; ooff = 3 * B + b;
            }
        }
        float2 av = __ldg((const float2*)Av + lane);
        float2 bv = __ldg((const float2*)Bv + lane);
        float lg = (d0 + av.x) * bv.x + (d1 + av.y) * bv.y;
        #pragma unroll
        for (int o = 16; o; o >>= 1) lg += __shfl_xor_sync(0xffffffffu, lg, o);
        if (lane == 0) out[ooff] = lg + bias;

        // reg1 += ||u1s||^2+||i1s||^2 (phase0,q0) ; reg2 += ||u2s||^2+||i2s||^2 (phase1,q1)
        if ((phase == 0 && q == 0) || (phase == 1 && q == 1))
            regacc += av.x * av.x + av.y * av.y + bv.x * bv.x + bv.y * bv.y;
    }

    // ---- block reduce reg loss, one atomic per block into out[4B + phase] ----
    #pragma unroll
    for (int o = 16; o; o >>= 1) regacc += __shfl_xor_sync(0xffffffffu, regacc, o);
    if (lane == 0) sred[warp] = regacc;
    __syncthreads();
    if (tid == 0)
        atomicAdd(out + 4 * B + phase, sred[0] + sred[1] + sred[2] + sred[3]);
}

extern "C" void kernel_launch(void* const* d_in, const int* in_sizes, int n_in,
                              void* d_out, int out_size) {
    const int B = in_sizes[0];
    float* out = (float*)d_out;

    zero_tail_kernel<<<1, 32>>>(out, 4 * B);
    fused_kernel<<<dim3(B, 2), NT>>>(
        (const int*)d_in[0], (const int*)d_in[1], (const int*)d_in[2], (const int*)d_in[3],
        (const int*)d_in[4], (const int*)d_in[5], (const int*)d_in[6],
        (const int*)d_in[7], (const int*)d_in[8], (const int*)d_in[9],
        (const float*)d_in[10], (const float*)d_in[11],
        (const float*)d_in[12], (const float*)d_in[13],
        (const float*)d_in[14],
        (const float*)d_in[15], (const float*)d_in[16],
        (const float*)d_in[17], (const float*)d_in[18],
        (const float*)d_in[19],
        (const float*)d_in[20], (const float*)d_in[21],
        (const float*)d_in[22], (const float*)d_in[23],
        out, B);
}